// round 5
// baseline (speedup 1.0000x reference)
#include <cuda_runtime.h>
#include <math.h>

#define Bq 16
#define Gq 32
#define Tq 4096
#define Dq 512
#define Kq 8
#define BG (Bq*Gq)          // 512
#define NWIN (Tq-3)         // 4093
#define NPAIR (NWIN-1)      // 4092
#define MPq 24
#define BINS 576

// ---------------- tables + scratch ----------------
__device__ float2 g_filt2[4*Tq];              // packed filter pairs, base-8 digit-reversed, /4096 folded
__device__ float2 g_tw[512];                  // exp(-2*pi*i*m/4096), m<512
__device__ int    g_lut[64];
__device__ float  g_pooled[(size_t)BG*Tq];    // 8 MB
__device__ float2 g_spec[(size_t)BG*Tq];      // 16 MB spectrum (physical layout)
__device__ float  g_energy[(size_t)BG*Kq*Tq]; // 64 MB mode energies
__device__ int    g_hist[BG*BINS];
__device__ float  g_part[BG*4*44];            // moment partials

// ---------------- helpers ----------------
__device__ __forceinline__ int swb(int e){ return e ^ ((e >> 4) & 7) ^ (((e >> 6) & 1) << 3); }
__device__ __forceinline__ int swt(int m){ return m ^ ((m >> 4) & 15); }
__device__ __forceinline__ float2 cadd(float2 a, float2 b){ return make_float2(a.x+b.x, a.y+b.y); }
__device__ __forceinline__ float2 csub(float2 a, float2 b){ return make_float2(a.x-b.x, a.y-b.y); }
__device__ __forceinline__ float2 cmul(float2 a, float2 b){ return make_float2(a.x*b.x - a.y*b.y, a.x*b.y + a.y*b.x); }
__device__ __forceinline__ float2 cmulc(float2 a, float2 b){ return make_float2(a.x*b.x + a.y*b.y, a.y*b.x - a.x*b.y); }

#define CSQ2 0.70710678118654752440f

__device__ __forceinline__ void dft8_fwd(float2* x) {
    float2 t0 = cadd(x[0], x[4]), t1 = csub(x[0], x[4]);
    float2 t2 = cadd(x[2], x[6]), t3 = csub(x[2], x[6]);
    float2 s0 = cadd(x[1], x[5]), s1 = csub(x[1], x[5]);
    float2 s2 = cadd(x[3], x[7]), s3 = csub(x[3], x[7]);
    float2 E0 = cadd(t0, t2), E2 = csub(t0, t2);
    float2 E1 = make_float2(t1.x + t3.y, t1.y - t3.x);
    float2 E3 = make_float2(t1.x - t3.y, t1.y + t3.x);
    float2 O0 = cadd(s0, s2), Oq = csub(s0, s2);
    float2 O1 = make_float2(s1.x + s3.y, s1.y - s3.x);
    float2 O3 = make_float2(s1.x - s3.y, s1.y + s3.x);
    float2 u1 = make_float2(CSQ2*(O1.x + O1.y), CSQ2*(O1.y - O1.x));
    float2 u2 = make_float2(Oq.y, -Oq.x);
    float2 u3 = make_float2(CSQ2*(O3.y - O3.x), -CSQ2*(O3.x + O3.y));
    x[0] = cadd(E0, O0); x[4] = csub(E0, O0);
    x[1] = cadd(E1, u1); x[5] = csub(E1, u1);
    x[2] = cadd(E2, u2); x[6] = csub(E2, u2);
    x[3] = cadd(E3, u3); x[7] = csub(E3, u3);
}

__device__ __forceinline__ void dft8_inv(float2* x) {
    float2 t0 = cadd(x[0], x[4]), t1 = csub(x[0], x[4]);
    float2 t2 = cadd(x[2], x[6]), t3 = csub(x[2], x[6]);
    float2 s0 = cadd(x[1], x[5]), s1 = csub(x[1], x[5]);
    float2 s2 = cadd(x[3], x[7]), s3 = csub(x[3], x[7]);
    float2 E0 = cadd(t0, t2), E2 = csub(t0, t2);
    float2 E1 = make_float2(t1.x - t3.y, t1.y + t3.x);
    float2 E3 = make_float2(t1.x + t3.y, t1.y - t3.x);
    float2 O0 = cadd(s0, s2), Oq = csub(s0, s2);
    float2 O1 = make_float2(s1.x - s3.y, s1.y + s3.x);
    float2 O3 = make_float2(s1.x + s3.y, s1.y - s3.x);
    float2 u1 = make_float2(CSQ2*(O1.x - O1.y), CSQ2*(O1.x + O1.y));
    float2 u2 = make_float2(-Oq.y, Oq.x);
    float2 u3 = make_float2(-CSQ2*(O3.x + O3.y), CSQ2*(O3.x - O3.y));
    x[0] = cadd(E0, O0); x[4] = csub(E0, O0);
    x[1] = cadd(E1, u1); x[5] = csub(E1, u1);
    x[2] = cadd(E2, u2); x[6] = csub(E2, u2);
    x[3] = cadd(E3, u3); x[7] = csub(E3, u3);
}

// ---------------- init ----------------
__device__ double filt_val(int idx, double cf) {
    double fr = (idx < Tq/2) ? (double)idx / Tq : (double)(idx - Tq) / Tq;
    double d = fabs(fr - cf) / 0.125;
    return exp(-0.5 * d * d);
}

__global__ void init_tables() {
    int j = blockIdx.x * blockDim.x + threadIdx.x;   // 4096 threads
    if (j < 512) {
        float a = -(float)j / 2048.0f;
        g_tw[j] = make_float2(cospif(a), sinpif(a));
    }
    if (j < Tq) {
        int f = ((j & 7) << 9) | (((j >> 3) & 7) << 6) | (((j >> 6) & 7) << 3) | ((j >> 9) & 7);
        int fc = (Tq - f) & (Tq - 1);
        #pragma unroll
        for (int p = 0; p < 4; p++) {
            double cf0 = -0.5 + (double)(2*p)   / 7.0;
            double cf1 = -0.5 + (double)(2*p+1) / 7.0;
            double g0 = 0.5 * (filt_val(f, cf0) + filt_val(fc, cf0)) / (double)Tq;
            double g1 = 0.5 * (filt_val(f, cf1) + filt_val(fc, cf1)) / (double)Tq;
            g_filt2[p*Tq + j] = make_float2((float)g0, (float)g1);
        }
    }
    for (int i = j; i < BG*BINS; i += 4096) g_hist[i] = 0;
    if (j == 0) {
        for (int q = 0; q < 64; q++) g_lut[q] = 0;
        for (int r0 = 0; r0 < 4; r0++)
        for (int r1 = 0; r1 < 4; r1++) { if (r1 == r0) continue;
        for (int r2 = 0; r2 < 4; r2++) { if (r2 == r0 || r2 == r1) continue;
            int r3 = 6 - r0 - r1 - r2;
            int rk[4] = {r0, r1, r2, r3};
            int si[4];
            for (int i = 0; i < 4; i++) si[rk[i]] = i;
            int key = (rk[0]>rk[1]) | ((rk[0]>rk[2])<<1) | ((rk[0]>rk[3])<<2)
                    | ((rk[1]>rk[2])<<3) | ((rk[1]>rk[3])<<4) | ((rk[2]>rk[3])<<5);
            int c0 = (si[0]>si[1]) + (si[0]>si[2]) + (si[0]>si[3]);
            int c1 = (si[1]>si[2]) + (si[1]>si[3]);
            int c2 = (si[2]>si[3]);
            g_lut[key] = 6*c0 + 2*c1 + c2;
        }}
    }
}

// ---------------- kernel P: coalesced pooling [B,T,D] -> g_pooled[bg][t] ----------------
__global__ void __launch_bounds__(256) pool_kernel(const float* __restrict__ hs) {
    __shared__ float sm[64][33];
    const int b  = blockIdx.x >> 6;
    const int t0 = (blockIdx.x & 63) * 64;
    const int wid = threadIdx.x >> 5, lane = threadIdx.x & 31;
    #pragma unroll
    for (int rr = 0; rr < 8; rr++) {
        int tr = wid * 8 + rr;
        const float4* row = (const float4*)(hs + ((size_t)b * Tq + t0 + tr) * Dq);
        #pragma unroll
        for (int pass = 0; pass < 4; pass++) {
            float4 v = row[pass*32 + lane];
            float s = v.x + v.y + v.z + v.w;
            s += __shfl_xor_sync(0xffffffffu, s, 1);
            s += __shfl_xor_sync(0xffffffffu, s, 2);
            if ((lane & 3) == 0) sm[tr][pass*8 + (lane >> 2)] = s * (1.0f/16.0f);
        }
    }
    __syncthreads();
    for (int i = threadIdx.x; i < 32*64; i += 256) {
        int g = i >> 6, tr = i & 63;
        g_pooled[((size_t)b * Gq + g) * Tq + t0 + tr] = sm[tr][g];
    }
}

#define DSM ((Tq + 512) * 8)   // buf 4096 float2 + stw 512 float2 = 36 KB

// ---------------- kernel A: forward radix-8 FFT -> g_spec ----------------
__global__ void __launch_bounds__(512, 2) fwd_kernel() {
    extern __shared__ float2 sh[];
    float2* buf = sh;
    float2* stw = sh + Tq;
    const int u = threadIdx.x;
    const int bg = blockIdx.x;

    if (u < 512) stw[swt(u)] = g_tw[u];
    const float* pooled = g_pooled + (size_t)bg * Tq;
    for (int t = u; t < Tq; t += 512) buf[swb(t)] = make_float2(pooled[t], 0.0f);
    __syncthreads();

    #pragma unroll
    for (int s = 0; s < 4; s++) {
        const int h  = 512 >> (3*s);
        const int tm = 1 << (3*s);
        int j = u & (h - 1);
        int i = ((u ^ j) << 3) | j;
        float2 x[8];
        #pragma unroll
        for (int c = 0; c < 8; c++) x[c] = buf[swb(i + c*h)];
        dft8_fwd(x);
        if (s < 3) {
            int m = j * tm;
            float2 w1 = stw[swt(m)];
            float2 w2 = cmul(w1, w1), w3 = cmul(w2, w1), w4 = cmul(w2, w2);
            float2 w5 = cmul(w3, w2), w6 = cmul(w3, w3), w7 = cmul(w4, w3);
            x[1] = cmul(x[1], w1); x[2] = cmul(x[2], w2); x[3] = cmul(x[3], w3);
            x[4] = cmul(x[4], w4); x[5] = cmul(x[5], w5); x[6] = cmul(x[6], w6);
            x[7] = cmul(x[7], w7);
        }
        #pragma unroll
        for (int c = 0; c < 8; c++) buf[swb(i + c*h)] = x[c];
        __syncthreads();
    }
    float2* dst = g_spec + (size_t)bg * Tq;
    for (int i = u; i < Tq; i += 512) dst[i] = buf[i];
}

// ---------------- kernel B: filter + inverse FFT + energies (reg-direct) + tmptm ----------------
__global__ void __launch_bounds__(512, 2) pair_kernel() {
    extern __shared__ float2 sh[];
    float2* W   = sh;
    float2* stw = sh + Tq;
    __shared__ int lut[64];
    __shared__ int hist[4*BINS];

    const int bg = blockIdx.x >> 2;
    const int p  = blockIdx.x & 3;
    const int u  = threadIdx.x;
    const int lane = u & 31;

    if (u < 512) stw[swt(u)] = g_tw[u];
    if (u < 64) lut[u] = g_lut[u];
    for (int i = u; i < 4*BINS; i += 512) hist[i] = 0;

    const float2* Xg = g_spec + (size_t)bg * Tq;
    const float2* fp = g_filt2 + p * Tq;
    for (int e = u; e < Tq; e += 512) {
        float2 x = Xg[swb(e)];
        float2 f = fp[e];
        W[swb(e)] = make_float2(x.x*f.x - x.y*f.y, x.x*f.y + x.y*f.x);
    }
    __syncthreads();

    float* e0 = g_energy + ((size_t)bg * Kq + 2*p)     * Tq;
    float* e1 = g_energy + ((size_t)bg * Kq + 2*p + 1) * Tq;

    #pragma unroll
    for (int s = 0; s < 4; s++) {
        const int h  = 1 << (3*s);
        const int tm = 512 >> (3*s);
        int j = u & (h - 1);
        int i = ((u ^ j) << 3) | j;
        float2 x[8];
        #pragma unroll
        for (int c = 0; c < 8; c++) x[c] = W[swb(i + c*h)];
        if (s > 0) {
            int m = j * tm;
            float2 w1 = stw[swt(m)];
            float2 w2 = cmul(w1, w1), w3 = cmul(w2, w1), w4 = cmul(w2, w2);
            float2 w5 = cmul(w3, w2), w6 = cmul(w3, w3), w7 = cmul(w4, w3);
            x[1] = cmulc(x[1], w1); x[2] = cmulc(x[2], w2); x[3] = cmulc(x[3], w3);
            x[4] = cmulc(x[4], w4); x[5] = cmulc(x[5], w5); x[6] = cmulc(x[6], w6);
            x[7] = cmulc(x[7], w7);
        }
        dft8_inv(x);
        if (s == 3) {
            // natural order: thread u holds t = u + 512c. Coalesced energy stores from regs.
            #pragma unroll
            for (int c = 0; c < 8; c++) {
                e0[u + 512*c] = x[c].x * x[c].x;
                e1[u + 512*c] = x[c].y * x[c].y;
            }
        }
        #pragma unroll
        for (int c = 0; c < 8; c++) W[swb(i + c*h)] = x[c];
        __syncthreads();
    }

    // tmptm: single-pass register sliding window, warp-aggregated shared atomics
    {
        int* myhist = hist + ((u >> 5) & 3) * BINS;
        const int base = u * 8;
        float2 v0 = W[swb(base)], v1 = W[swb(base+1)], v2 = W[swb(base+2)], v3 = W[swb(base+3)];
        int kx = (v0.x>v1.x) | ((v0.x>v2.x)<<1) | ((v0.x>v3.x)<<2)
               | ((v1.x>v2.x)<<3) | ((v1.x>v3.x)<<4) | ((v2.x>v3.x)<<5);
        int ky = (v0.y>v1.y) | ((v0.y>v2.y)<<1) | ((v0.y>v3.y)<<2)
               | ((v1.y>v2.y)<<3) | ((v1.y>v3.y)<<4) | ((v2.y>v3.y)<<5);
        int px = lut[kx], py = lut[ky];
        #pragma unroll
        for (int i = 0; i < 8; i++) {
            int sidx = base + 4 + i; sidx = min(sidx, Tq - 1);
            float2 v4 = W[swb(sidx)];
            kx = ((kx>>3)&1) | (((kx>>4)&1)<<1) | ((v1.x>v4.x)<<2)
               | (((kx>>5)&1)<<3) | ((v2.x>v4.x)<<4) | ((v3.x>v4.x)<<5);
            ky = ((ky>>3)&1) | (((ky>>4)&1)<<1) | ((v1.y>v4.y)<<2)
               | (((ky>>5)&1)<<3) | ((v2.y>v4.y)<<4) | ((v3.y>v4.y)<<5);
            int cx = lut[kx], cy = lut[ky];
            int n = base + i;
            bool valid = (n < NPAIR);
            int linx = valid ? (px * MPq + cx) : (BINS + lane);
            unsigned mx = __match_any_sync(0xffffffffu, linx);
            if (valid && lane == (__ffs(mx) - 1)) atomicAdd(&myhist[linx], __popc(mx));
            int liny = valid ? (py * MPq + cy) : (BINS + lane);
            unsigned my = __match_any_sync(0xffffffffu, liny);
            if (valid && lane == (__ffs(my) - 1)) atomicAdd(&myhist[liny], __popc(my));
            px = cx; py = cy;
            v1 = v2; v2 = v3; v3 = v4;
        }
    }
    __syncthreads();

    for (int i = u; i < BINS; i += 512) {
        int s = hist[i] + hist[BINS + i] + hist[2*BINS + i] + hist[3*BINS + i];
        if (s) atomicAdd(&g_hist[bg*BINS + i], s);
    }
}

// ---------------- kernel C1: moment partials (grid BG*4) ----------------
__global__ void __launch_bounds__(256) mom_kernel() {
    const int bg = blockIdx.x >> 2;
    const int ch = blockIdx.x & 3;
    const int tid = threadIdx.x;
    const float4* base = (const float4*)(g_energy + (size_t)bg * Kq * Tq);
    const int idx4 = ch * 256 + tid;   // one float4 per mode per thread

    float4 E[Kq];
    #pragma unroll
    for (int k = 0; k < Kq; k++) E[k] = base[k * (Tq/4) + idx4];

    float s1[Kq]; float s2[36];
    #pragma unroll
    for (int k = 0; k < Kq; k++) s1[k] = E[k].x + E[k].y + E[k].z + E[k].w;
    int idx = 0;
    #pragma unroll
    for (int k = 0; k < Kq; k++)
        #pragma unroll
        for (int l = k; l < Kq; l++)
            s2[idx++] = E[k].x*E[l].x + E[k].y*E[l].y + E[k].z*E[l].z + E[k].w*E[l].w;

    __shared__ float red[44];
    if (tid < 44) red[tid] = 0.0f;
    __syncthreads();
    #pragma unroll
    for (int i = 0; i < Kq; i++) {
        float v = s1[i];
        #pragma unroll
        for (int o = 16; o; o >>= 1) v += __shfl_down_sync(0xffffffffu, v, o);
        if ((tid & 31) == 0) atomicAdd(&red[i], v);
    }
    #pragma unroll
    for (int i = 0; i < 36; i++) {
        float v = s2[i];
        #pragma unroll
        for (int o = 16; o; o >>= 1) v += __shfl_down_sync(0xffffffffu, v, o);
        if ((tid & 31) == 0) atomicAdd(&red[8 + i], v);
    }
    __syncthreads();
    if (tid < 44) g_part[blockIdx.x * 44 + tid] = red[tid];
}

// ---------------- kernel C2: merge + outputs ----------------
__global__ void __launch_bounds__(256) final2_kernel(float* __restrict__ out) {
    const int bg = blockIdx.x, tid = threadIdx.x;
    const float invs = 1.0f / (float)(Kq * NPAIR);
    for (int i = tid; i < BINS; i += 256)
        out[(size_t)bg * BINS + i] = (float)g_hist[bg*BINS + i] * invs;

    __shared__ float red[44];
    if (tid < 44) {
        float v = 0.0f;
        #pragma unroll
        for (int c = 0; c < 4; c++) v += g_part[(bg*4 + c) * 44 + tid];
        red[tid] = v;
    }
    __syncthreads();

    if (tid < 28) {
        float* out2 = out + (size_t)BG * BINS;
        int k = 0, rem = tid;
        while (rem >= 7 - k) { rem -= 7 - k; k++; }
        int l = k + 1 + rem;
        float S1k = red[k], S1l = red[l];
        int dk = 8 + (k * (17 - k)) / 2;
        int dl = 8 + (l * (17 - l)) / 2;
        float S2kk = red[dk], S2ll = red[dl];
        int off = k * 8 - (k * (k - 1)) / 2 + (l - k);
        float S2kl = red[8 + off];
        const float Tf = (float)Tq;
        float vk = (S2kk - S1k * S1k / Tf) / (Tf - 1.0f);
        float vl = (S2ll - S1l * S1l / Tf) / (Tf - 1.0f);
        float sk = fmaxf(sqrtf(fmaxf(vk, 0.0f)), 1e-8f);
        float sl = fmaxf(sqrtf(fmaxf(vl, 0.0f)), 1e-8f);
        float corr = (S2kl - S1k * S1l / Tf) / (Tf * sk * sl);
        out2[(size_t)bg * 28 + tid] = corr;
    }
}

// ---------------- launch ----------------
extern "C" void kernel_launch(void* const* d_in, const int* in_sizes, int n_in,
                              void* d_out, int out_size) {
    const float* hs = (const float*)d_in[0];
    float* out = (float*)d_out;

    init_tables<<<16, 256>>>();
    pool_kernel<<<Bq*64, 256>>>(hs);
    cudaFuncSetAttribute(fwd_kernel,  cudaFuncAttributeMaxDynamicSharedMemorySize, DSM);
    cudaFuncSetAttribute(pair_kernel, cudaFuncAttributeMaxDynamicSharedMemorySize, DSM);
    fwd_kernel<<<BG, 512, DSM>>>();
    pair_kernel<<<BG*4, 512, DSM>>>();
    mom_kernel<<<BG*4, 256>>>();
    final2_kernel<<<BG, 256>>>(out);
}